// round 15
// baseline (speedup 1.0000x reference)
#include <cuda_runtime.h>
#include <cuda_fp16.h>
#include <cstdint>

// B=4, T=1024, C=1024, H=16, D=64, BH=64
#define NT 1024
#define NC 1024

// ---------------- scratch (all fp16, half2-packed in uints) ----------------
__device__ unsigned g_xh  [4096 * 512];         // x as half2: [m][512]u
__device__ unsigned g_wp  [4 * 512 * 1024];     // per z: [k2][n] half2
__device__ unsigned g_q   [64 * 1024 * 32];     // [BH][T][32]u (pre-scaled 1/8)
__device__ unsigned g_k   [64 * 1024 * 32];     // [BH][T][32]u
__device__ unsigned g_vt  [64 * 64 * 512];      // [BH][D][512]u (transposed)
__device__ unsigned g_attn[4096 * 512];         // [B*T][512]u
__device__ float    g_proj[4 * 1024 * 1024];    // [B,T,C]

// ---------------- helpers ----------------
__device__ __forceinline__ unsigned h2(float lo, float hi) {
    __half2 h = __floats2half2_rn(lo, hi);
    return *reinterpret_cast<unsigned*>(&h);
}
__device__ __forceinline__ uint4 pack8(float4 a, float4 b) {
    uint4 t;
    t.x = h2(a.x, a.y); t.y = h2(a.z, a.w);
    t.z = h2(b.x, b.y); t.w = h2(b.z, b.w);
    return t;
}
__device__ __forceinline__ void mma16(float* c, const unsigned* a, const unsigned* b) {
    asm volatile(
        "mma.sync.aligned.m16n8k16.row.col.f32.f16.f16.f32 "
        "{%0,%1,%2,%3}, {%4,%5,%6,%7}, {%8,%9}, {%0,%1,%2,%3};"
        : "+f"(c[0]), "+f"(c[1]), "+f"(c[2]), "+f"(c[3])
        : "r"(a[0]), "r"(a[1]), "r"(a[2]), "r"(a[3]), "r"(b[0]), "r"(b[1]));
}
__device__ __forceinline__ unsigned smaddr(const void* p) {
    return (unsigned)__cvta_generic_to_shared(p);
}
__device__ __forceinline__ void ldsm4(unsigned* r, unsigned a) {
    asm volatile("ldmatrix.sync.aligned.m8n8.x4.shared.b16 {%0,%1,%2,%3}, [%4];"
                 : "=r"(r[0]), "=r"(r[1]), "=r"(r[2]), "=r"(r[3]) : "r"(a));
}
__device__ __forceinline__ void cpasync16(unsigned dst, const void* src) {
    asm volatile("cp.async.cg.shared.global [%0], [%1], 16;"
                 :: "r"(dst), "l"(src) : "memory");
}
__device__ __forceinline__ void cpasync_commit() {
    asm volatile("cp.async.commit_group;" ::: "memory");
}
__device__ __forceinline__ void cpasync_wait0() {
    asm volatile("cp.async.wait_group 0;" ::: "memory");
}

// =====================================================================
// Prep 1: x fp32 -> half2-packed g_xh.
// =====================================================================
__global__ __launch_bounds__(256) void cvt_x_kernel(const float* __restrict__ x)
{
    int idx = blockIdx.x * 256 + threadIdx.x;
    float4 a = ((const float4*)x)[idx * 2];
    float4 b = ((const float4*)x)[idx * 2 + 1];
    ((uint4*)g_xh)[idx] = pack8(a, b);
}

// =====================================================================
// Prep 2: W fp32 [k][n] -> k-pair-packed half2 g_wp[z][k2][n].
// =====================================================================
__global__ __launch_bounds__(256) void pack_w_kernel(
    const float* __restrict__ Wq, const float* __restrict__ Wk,
    const float* __restrict__ Wv, const float* __restrict__ Wo)
{
    const int z = blockIdx.z;
    const float* __restrict__ W = (z == 0) ? Wq : (z == 1) ? Wk : (z == 2) ? Wv : Wo;
    int idx = blockIdx.x * 256 + threadIdx.x;
    int k2 = idx >> 8;
    int n4 = (idx & 255) * 4;
    float4 r0 = *(const float4*)(W + (size_t)(2 * k2) * NC + n4);
    float4 r1 = *(const float4*)(W + (size_t)(2 * k2 + 1) * NC + n4);
    uint4 o;
    o.x = h2(r0.x, r1.x); o.y = h2(r0.y, r1.y);
    o.z = h2(r0.z, r1.z); o.w = h2(r0.w, r1.w);
    ((uint4*)(g_wp + (size_t)z * 524288))[idx] = o;
}

// =====================================================================
// Kernel 1: fused QKV projection (fp16 m16n8k16), double-buffered,
// A-fragments via ldmatrix.x4, B-fragments scalar.  (unchanged R14)
// =====================================================================
__global__ __launch_bounds__(256) void qkv_kernel(
    const float* __restrict__ bq, const float* __restrict__ bk,
    const float* __restrict__ bv)
{
    __shared__ unsigned As[2][128 * 20];
    __shared__ unsigned Bs[2][16 * 132];

    const int z = blockIdx.z;
    const float* __restrict__ bias = (z == 0) ? bq : (z == 1) ? bk : bv;
    const unsigned* __restrict__ Wp = g_wp + (size_t)z * 524288;

    const int tid  = threadIdx.x;
    const int wid  = tid >> 5, lane = tid & 31;
    const int g    = lane >> 2, tg = lane & 3;
    const int r8   = lane & 7,  qd = lane >> 3;
    const int bm   = blockIdx.y * 128, bn = blockIdx.x * 128;
    const int wm   = wid & 1, wn = wid >> 1;

    const int ar0 = tid >> 2,  ac4 = (tid & 3) * 4;
    const int br0 = tid >> 5,  bc4 = (tid & 31) * 4;

    const unsigned aSb = smaddr(&As[0][(wm * 64 + (qd & 1) * 8 + r8) * 20 + (qd >> 1) * 4]);

    uint4 aR[2], bR[2];
    #pragma unroll
    for (int i = 0; i < 2; i++) {
        aR[i] = *(const uint4*)(g_xh + (size_t)(bm + ar0 + 64 * i) * 512 + ac4);
        bR[i] = *(const uint4*)(Wp + (size_t)(br0 + 8 * i) * 1024 + bn + bc4);
    }
    #pragma unroll
    for (int i = 0; i < 2; i++) {
        *(uint4*)&As[0][(ar0 + 64 * i) * 20 + ac4] = aR[i];
        *(uint4*)&Bs[0][(br0 + 8 * i) * 132 + bc4] = bR[i];
    }
    __syncthreads();

    float acc[4][4][4];
    #pragma unroll
    for (int a = 0; a < 4; a++)
        #pragma unroll
        for (int b = 0; b < 4; b++)
            #pragma unroll
            for (int c = 0; c < 4; c++) acc[a][b][c] = 0.f;

    for (int kt = 0; kt < 32; ++kt) {
        const unsigned* Bc = Bs[kt & 1];
        const unsigned aOff = (kt & 1) * 2560u;

        if (kt < 31) {
            #pragma unroll
            for (int i = 0; i < 2; i++) {
                aR[i] = *(const uint4*)(g_xh + (size_t)(bm + ar0 + 64 * i) * 512
                                        + (kt + 1) * 16 + ac4);
                bR[i] = *(const uint4*)(Wp + (size_t)((kt + 1) * 16 + br0 + 8 * i) * 1024
                                        + bn + bc4);
            }
        }
        #pragma unroll
        for (int ks = 0; ks < 2; ks++) {
            const int ku = ks * 8;
            unsigned af[4][4], bf[4][2];
            #pragma unroll
            for (int mt = 0; mt < 4; mt++)
                ldsm4(af[mt], aSb + (aOff + mt * (16 * 20) + ku) * 4);
            #pragma unroll
            for (int nt = 0; nt < 4; nt++) {
                int c0 = wn * 32 + nt * 8 + g;
                bf[nt][0] = Bc[(ku + tg) * 132 + c0];
                bf[nt][1] = Bc[(ku + tg + 4) * 132 + c0];
            }
            #pragma unroll
            for (int mt = 0; mt < 4; mt++)
                #pragma unroll
                for (int nt = 0; nt < 4; nt++)
                    mma16(acc[mt][nt], af[mt], bf[nt]);
        }
        if (kt < 31) {
            unsigned* An = As[(kt + 1) & 1];
            unsigned* Bn = Bs[(kt + 1) & 1];
            #pragma unroll
            for (int i = 0; i < 2; i++) {
                *(uint4*)&An[(ar0 + 64 * i) * 20 + ac4] = aR[i];
                *(uint4*)&Bn[(br0 + 8 * i) * 132 + bc4] = bR[i];
            }
            __syncthreads();
        }
    }

    __half* vt_h = (__half*)g_vt;
    #pragma unroll
    for (int mt = 0; mt < 4; mt++) {
        #pragma unroll
        for (int nt = 0; nt < 4; nt++) {
            int row = bm + wm * 64 + mt * 16 + g;
            int col = bn + wn * 32 + nt * 8 + tg * 2;
            float b0 = bias[col], b1 = bias[col + 1];
            #pragma unroll
            for (int hf = 0; hf < 2; hf++) {
                int m  = row + hf * 8;
                int bb = m >> 10, t = m & 1023;
                int h  = col >> 6, d = col & 63;
                int bh = bb * 16 + h;
                float v0 = acc[mt][nt][hf * 2 + 0] + b0;
                float v1 = acc[mt][nt][hf * 2 + 1] + b1;
                if (z == 0) {
                    g_q[((size_t)(bh * 1024 + t)) * 32 + d / 2] = h2(v0 * 0.125f, v1 * 0.125f);
                } else if (z == 1) {
                    g_k[((size_t)(bh * 1024 + t)) * 32 + d / 2] = h2(v0, v1);
                } else {
                    vt_h[((size_t)(bh * 64 + d)) * 1024 + t]     = __float2half(v0);
                    vt_h[((size_t)(bh * 64 + d + 1)) * 1024 + t] = __float2half(v1);
                }
            }
        }
    }
}

// =====================================================================
// Kernel 2: FLASH attention — double-buffered K/V/M via cp.async,
// ONE __syncthreads per tile.  ldmatrix fragments throughout.
// =====================================================================
__global__ __launch_bounds__(256, 1) void flash_kernel(const int* __restrict__ mask)
{
    extern __shared__ unsigned sm[];
    unsigned* Qs = sm;                          // [128][36]
    unsigned* Ks = Qs + 4608;                   // 2 x [128][36]
    unsigned* Vs = Ks + 2 * 4608;               // 2 x [64][68]
    unsigned* Ps = Vs + 2 * 4352;               // [128][68]
    int*      Ms = (int*)(Ps + 8704);           // 2 x [128]

    const int bh  = blockIdx.y;
    const int bq  = blockIdx.x * 128;
    const int tid = threadIdx.x;
    const int w   = tid >> 5, lane = tid & 31;
    const int g   = lane >> 2, tg = lane & 3;
    const int r8  = lane & 7,  qd = lane >> 3;

    const unsigned* qptr  = g_q + ((size_t)bh * NT + bq) * 32;
    const unsigned* kbase = g_k + (size_t)bh * NT * 32;
    const unsigned* vbase = g_vt + (size_t)bh * 64 * 512;
    const int*      mrow  = mask + (bh >> 4) * NT;

    const unsigned aQb = smaddr(&Qs[(w * 16 + (qd & 1) * 8 + r8) * 36 + (qd >> 1) * 4]);
    const unsigned bKb = smaddr(&Ks[((qd >> 1) * 8 + r8) * 36 + (qd & 1) * 4]);
    const unsigned aPb = smaddr(&Ps[(w * 16 + (qd & 1) * 8 + r8) * 68 + (qd >> 1) * 4]);
    const unsigned bVb = smaddr(&Vs[((qd >> 1) * 8 + r8) * 68 + (qd & 1) * 4]);

    // producer addressing (reused by prologue + cp.async)
    const int rk = tid >> 3, ck = (tid & 7) * 4;     // K: +32 rows per task
    const int rv = tid >> 4, cv = (tid & 15) * 4;    // V: +16 rows per task

    // ---- prologue: Q + tile 0 (synchronous) ----
    #pragma unroll
    for (int i = 0; i < 4; i++) {
        int idx = tid + 256 * i;
        int r = idx >> 3, c4 = (idx & 7) * 4;
        *(uint4*)&Qs[r * 36 + c4] = *(const uint4*)(qptr + (size_t)r * 32 + c4);
        *(uint4*)&Ks[r * 36 + c4] = *(const uint4*)(kbase + (size_t)r * 32 + c4);
    }
    #pragma unroll
    for (int i = 0; i < 4; i++) {
        int idx = tid + 256 * i;
        int r = idx >> 4, c4 = (idx & 15) * 4;
        *(uint4*)&Vs[r * 68 + c4] = *(const uint4*)(vbase + (size_t)r * 512 + c4);
    }
    if (tid < 128) Ms[tid] = mrow[tid];

    float l0 = 0.f, l1 = 0.f;
    float o[8][4];
    #pragma unroll
    for (int i = 0; i < 8; i++)
        #pragma unroll
        for (int j = 0; j < 4; j++) o[i][j] = 0.f;

    const int r0p = (w * 16 + g) * 68;
    const int r1p = (w * 16 + 8 + g) * 68;

    for (int t = 0; t < 8; t++) {
        const int cur = t & 1, alt = cur ^ 1;
        cpasync_wait0();                 // my tile-t copies have landed
        __syncthreads();                 // everyone's copies landed; alt buffer free

        // ---- issue cp.async for tile t+1 into alt buffer ----
        if (t < 7) {
            const int tn = (t + 1) * 128;
            #pragma unroll
            for (int i = 0; i < 4; i++) {
                int idx = tid + 256 * i;
                int r = (idx >> 3), c4 = (idx & 7) * 4;
                cpasync16(smaddr(&Ks[alt * 4608 + r * 36 + c4]),
                          kbase + (size_t)(tn + r) * 32 + c4);
                int r2 = (idx >> 4), c42 = (idx & 15) * 4;
                cpasync16(smaddr(&Vs[alt * 4352 + r2 * 68 + c42]),
                          vbase + (size_t)r2 * 512 + tn / 2 + c42);
            }
            if (tid < 32)
                cpasync16(smaddr(&Ms[alt * 128 + tid * 4]), mrow + tn + tid * 4);
            cpasync_commit();
        }

        const unsigned kOff = cur * 4608u * 4u;   // bytes
        const unsigned vOff = cur * 4352u * 4u;
        const int*     Mc   = Ms + cur * 128;

        // ---- S = Q @ K^T ----
        float s[16][4];
        #pragma unroll
        for (int nt = 0; nt < 16; nt++)
            #pragma unroll
            for (int c = 0; c < 4; c++) s[nt][c] = 0.f;

        #pragma unroll
        for (int ks = 0; ks < 4; ks++) {
            const int ku = ks * 8;
            unsigned af[4];
            ldsm4(af, aQb + ku * 4);
            #pragma unroll
            for (int ntp = 0; ntp < 8; ntp++) {
                unsigned bf[4];
                ldsm4(bf, bKb + kOff + (ntp * (16 * 36) + ku) * 4);
                mma16(s[2 * ntp],     af, bf);
                mma16(s[2 * ntp + 1], af, bf + 2);
            }
        }

        // ---- P = exp(S) * mask -> smem, partial sums ----
        #pragma unroll
        for (int nt = 0; nt < 16; nt++) {
            int c0 = nt * 8 + tg * 2;
            float fm0 = (Mc[c0]     != 0) ? 1.f : 0.f;
            float fm1 = (Mc[c0 + 1] != 0) ? 1.f : 0.f;
            float p0 = __expf(s[nt][0]) * fm0;
            float p1 = __expf(s[nt][1]) * fm1;
            float p2 = __expf(s[nt][2]) * fm0;
            float p3 = __expf(s[nt][3]) * fm1;
            l0 += p0 + p1;
            l1 += p2 + p3;
            Ps[r0p + nt * 4 + tg] = h2(p0, p1);
            Ps[r1p + nt * 4 + tg] = h2(p2, p3);
        }

        __syncwarp();                    // Ps rows are warp-private

        // ---- O += P @ V ----
        #pragma unroll
        for (int ks = 0; ks < 8; ks++) {
            const int ku = ks * 8;
            unsigned af[4];
            ldsm4(af, aPb + ku * 4);
            #pragma unroll
            for (int ntp = 0; ntp < 4; ntp++) {
                unsigned bf[4];
                ldsm4(bf, bVb + vOff + (ntp * (16 * 68) + ku) * 4);
                mma16(o[2 * ntp],     af, bf);
                mma16(o[2 * ntp + 1], af, bf + 2);
            }
        }
    }

    // ---- epilogue ----
    #pragma unroll
    for (int off = 1; off <= 2; off <<= 1) {
        l0 += __shfl_xor_sync(0xffffffffu, l0, off);
        l1 += __shfl_xor_sync(0xffffffffu, l1, off);
    }
    const int b_ = bh >> 4, h = bh & 15;
    float inv0 = 1.0f / l0, inv1 = 1.0f / l1;
    #pragma unroll
    for (int nt = 0; nt < 8; nt++) {
        int d = nt * 8 + tg * 2;
        int q0 = bq + w * 16 + g;
        g_attn[((size_t)(b_ * 1024 + q0)) * 512 + (h * 64 + d) / 2]
            = h2(o[nt][0] * inv0, o[nt][1] * inv0);
        g_attn[((size_t)(b_ * 1024 + q0 + 8)) * 512 + (h * 64 + d) / 2]
            = h2(o[nt][2] * inv1, o[nt][3] * inv1);
    }
}

// =====================================================================
// Kernel 3: output projection — A via ldmatrix, B scalar. (unchanged)
// =====================================================================
__global__ __launch_bounds__(256) void proj_kernel(const float* __restrict__ bo)
{
    __shared__ unsigned As[2][128 * 20];
    __shared__ unsigned Bs[2][16 * 132];

    const unsigned* __restrict__ Wp = g_wp + (size_t)3 * 524288;

    const int tid  = threadIdx.x;
    const int wid  = tid >> 5, lane = tid & 31;
    const int g    = lane >> 2, tg = lane & 3;
    const int r8   = lane & 7,  qd = lane >> 3;
    const int bm   = blockIdx.y * 128, bn = blockIdx.x * 128;
    const int wm   = wid & 1, wn = wid >> 1;

    const int ar0 = tid >> 2,  ac4 = (tid & 3) * 4;
    const int br0 = tid >> 5,  bc4 = (tid & 31) * 4;

    const unsigned aSb = smaddr(&As[0][(wm * 64 + (qd & 1) * 8 + r8) * 20 + (qd >> 1) * 4]);

    uint4 aR[2], bR[2];
    #pragma unroll
    for (int i = 0; i < 2; i++) {
        aR[i] = *(const uint4*)(g_attn + (size_t)(bm + ar0 + 64 * i) * 512 + ac4);
        bR[i] = *(const uint4*)(Wp + (size_t)(br0 + 8 * i) * 1024 + bn + bc4);
    }
    #pragma unroll
    for (int i = 0; i < 2; i++) {
        *(uint4*)&As[0][(ar0 + 64 * i) * 20 + ac4] = aR[i];
        *(uint4*)&Bs[0][(br0 + 8 * i) * 132 + bc4] = bR[i];
    }
    __syncthreads();

    float acc[4][4][4];
    #pragma unroll
    for (int a = 0; a < 4; a++)
        #pragma unroll
        for (int b = 0; b < 4; b++)
            #pragma unroll
            for (int c = 0; c < 4; c++) acc[a][b][c] = 0.f;

    for (int kt = 0; kt < 32; ++kt) {
        const unsigned* Bc = Bs[kt & 1];
        const unsigned aOff = (kt & 1) * 2560u;

        if (kt < 31) {
            #pragma unroll
            for (int i = 0; i < 2; i++) {
                aR[i] = *(const uint4*)(g_attn + (size_t)(bm + ar0 + 64 * i) * 512
                                        + (kt + 1) * 16 + ac4);
                bR[i] = *(const uint4*)(Wp + (size_t)((kt + 1) * 16 + br0 + 8 * i) * 1024
                                        + bn + bc4);
            }
        }
        #pragma unroll
        for (int ks = 0; ks < 2; ks++) {
            const int ku = ks * 8;
            unsigned af[4][4], bf[4][2];
            #pragma unroll
            for (int mt = 0; mt < 4; mt++)
                ldsm4(af[mt], aSb + (aOff + mt * (16 * 20) + ku) * 4);
            #pragma unroll
            for (int nt = 0; nt < 4; nt++) {
                int c0 = wn * 32 + nt * 8 + g;
                bf[nt][0] = Bc[(ku + tg) * 132 + c0];
                bf[nt][1] = Bc[(ku + tg + 4) * 132 + c0];
            }
            #pragma unroll
            for (int mt = 0; mt < 4; mt++)
                #pragma unroll
                for (int nt = 0; nt < 4; nt++)
                    mma16(acc[mt][nt], af[mt], bf[nt]);
        }
        if (kt < 31) {
            unsigned* An = As[(kt + 1) & 1];
            unsigned* Bn = Bs[(kt + 1) & 1];
            #pragma unroll
            for (int i = 0; i < 2; i++) {
                *(uint4*)&An[(ar0 + 64 * i) * 20 + ac4] = aR[i];
                *(uint4*)&Bn[(br0 + 8 * i) * 132 + bc4] = bR[i];
            }
            __syncthreads();
        }
    }

    #pragma unroll
    for (int mt = 0; mt < 4; mt++) {
        #pragma unroll
        for (int nt = 0; nt < 4; nt++) {
            int row = bm + wm * 64 + mt * 16 + g;
            int col = bn + wn * 32 + nt * 8 + tg * 2;
            float b0 = bo[col], b1 = bo[col + 1];
            #pragma unroll
            for (int hf = 0; hf < 2; hf++) {
                int m = row + hf * 8;
                float2 val = make_float2(acc[mt][nt][hf * 2 + 0] + b0,
                                         acc[mt][nt][hf * 2 + 1] + b1);
                *(float2*)&g_proj[(size_t)m * NC + col] = val;
            }
        }
    }
}

// =====================================================================
// Kernel 4: LayerNorm.
// =====================================================================
__global__ __launch_bounds__(256) void ln_kernel(
    const float* __restrict__ gamma, const float* __restrict__ beta,
    float* __restrict__ out)
{
    __shared__ float redS[8];
    __shared__ float redQ[8];
    const int tid = threadIdx.x;
    const float* p = g_proj + (size_t)blockIdx.x * NC;

    float4 v = ((const float4*)p)[tid];
    float s  = v.x + v.y + v.z + v.w;
    float ss = v.x * v.x + v.y * v.y + v.z * v.z + v.w * v.w;
    #pragma unroll
    for (int o = 16; o > 0; o >>= 1) {
        s  += __shfl_xor_sync(0xffffffffu, s,  o);
        ss += __shfl_xor_sync(0xffffffffu, ss, o);
    }
    if ((tid & 31) == 0) { redS[tid >> 5] = s; redQ[tid >> 5] = ss; }
    __syncthreads();
    float S = 0.f, Q = 0.f;
    #pragma unroll
    for (int w = 0; w < 8; w++) { S += redS[w]; Q += redQ[w]; }

    float mu  = S * (1.0f / 1024.0f);
    float var = Q * (1.0f / 1024.0f) - mu * mu;
    var = fmaxf(var, 0.0f);
    float rstd = rsqrtf(var + 1e-5f);

    float4 gv = ((const float4*)gamma)[tid];
    float4 bv = ((const float4*)beta)[tid];
    float4 o;
    o.x = (v.x - mu) * rstd * gv.x + bv.x;
    o.y = (v.y - mu) * rstd * gv.y + bv.y;
    o.z = (v.z - mu) * rstd * gv.z + bv.z;
    o.w = (v.w - mu) * rstd * gv.w + bv.w;
    ((float4*)(out + (size_t)blockIdx.x * NC))[tid] = o;
}

// =====================================================================
extern "C" void kernel_launch(void* const* d_in, const int* in_sizes, int n_in,
                              void* d_out, int out_size)
{
    const float* x    = (const float*)d_in[0];
    const int*   mask = (const int*)  d_in[1];
    const float* Wq   = (const float*)d_in[2];
    const float* bq   = (const float*)d_in[3];
    const float* Wk   = (const float*)d_in[4];
    const float* bk   = (const float*)d_in[5];
    const float* Wv   = (const float*)d_in[6];
    const float* bv   = (const float*)d_in[7];
    const float* Wo   = (const float*)d_in[8];
    const float* bo   = (const float*)d_in[9];
    const float* lg   = (const float*)d_in[10];
    const float* lb   = (const float*)d_in[11];
    float* out = (float*)d_out;

    // Qs + 2*Ks + 2*Vs + Ps (uints) + 2*Ms (ints)
    const int FLASH_SMEM = (4608 + 2 * 4608 + 2 * 4352 + 8704) * 4 + 2 * 128 * 4;
    cudaFuncSetAttribute(flash_kernel,
                         cudaFuncAttributeMaxDynamicSharedMemorySize, FLASH_SMEM);

    cvt_x_kernel <<<2048, 256>>>(x);
    pack_w_kernel<<<dim3(512, 1, 4), 256>>>(Wq, Wk, Wv, Wo);
    qkv_kernel   <<<dim3(8, 32, 3), 256>>>(bq, bk, bv);
    flash_kernel <<<dim3(8, 64), 256, FLASH_SMEM>>>(mask);
    proj_kernel  <<<dim3(8, 32), 256>>>(bo);
    ln_kernel    <<<4096, 256>>>(lg, lb, out);
}

// round 16
// speedup vs baseline: 1.1045x; 1.1045x over previous
#include <cuda_runtime.h>
#include <cuda_fp16.h>
#include <cstdint>

// B=4, T=1024, C=1024, H=16, D=64, BH=64
#define NT 1024
#define NC 1024

// ---------------- scratch (all fp16, half2-packed in uints) ----------------
__device__ unsigned g_xh  [4096 * 512];         // x as half2: [m][512]u
__device__ unsigned g_wp  [4 * 512 * 1024];     // per z: [k2][n] half2
__device__ unsigned g_q   [64 * 1024 * 32];     // [BH][T][32]u (pre-scaled 1/8)
__device__ unsigned g_k   [64 * 1024 * 32];     // [BH][T][32]u
__device__ unsigned g_vt  [64 * 64 * 512];      // [BH][D][512]u (transposed)
__device__ unsigned g_attn[4096 * 512];         // [B*T][512]u
__device__ float    g_proj[4 * 1024 * 1024];    // [B,T,C]

// ---------------- helpers ----------------
__device__ __forceinline__ unsigned h2(float lo, float hi) {
    __half2 h = __floats2half2_rn(lo, hi);
    return *reinterpret_cast<unsigned*>(&h);
}
__device__ __forceinline__ uint4 pack8(float4 a, float4 b) {
    uint4 t;
    t.x = h2(a.x, a.y); t.y = h2(a.z, a.w);
    t.z = h2(b.x, b.y); t.w = h2(b.z, b.w);
    return t;
}
__device__ __forceinline__ void mma16(float* c, const unsigned* a, const unsigned* b) {
    asm volatile(
        "mma.sync.aligned.m16n8k16.row.col.f32.f16.f16.f32 "
        "{%0,%1,%2,%3}, {%4,%5,%6,%7}, {%8,%9}, {%0,%1,%2,%3};"
        : "+f"(c[0]), "+f"(c[1]), "+f"(c[2]), "+f"(c[3])
        : "r"(a[0]), "r"(a[1]), "r"(a[2]), "r"(a[3]), "r"(b[0]), "r"(b[1]));
}
__device__ __forceinline__ unsigned smaddr(const void* p) {
    return (unsigned)__cvta_generic_to_shared(p);
}
__device__ __forceinline__ void ldsm4(unsigned* r, unsigned a) {
    asm volatile("ldmatrix.sync.aligned.m8n8.x4.shared.b16 {%0,%1,%2,%3}, [%4];"
                 : "=r"(r[0]), "=r"(r[1]), "=r"(r[2]), "=r"(r[3]) : "r"(a));
}
__device__ __forceinline__ void cpasync16(unsigned dst, const void* src) {
    asm volatile("cp.async.cg.shared.global [%0], [%1], 16;"
                 :: "r"(dst), "l"(src) : "memory");
}
__device__ __forceinline__ void cpasync_commit() {
    asm volatile("cp.async.commit_group;" ::: "memory");
}
__device__ __forceinline__ void cpasync_wait0() {
    asm volatile("cp.async.wait_group 0;" ::: "memory");
}

// =====================================================================
// Prep 1: x fp32 -> half2-packed g_xh.
// =====================================================================
__global__ __launch_bounds__(256) void cvt_x_kernel(const float* __restrict__ x)
{
    int idx = blockIdx.x * 256 + threadIdx.x;
    float4 a = ((const float4*)x)[idx * 2];
    float4 b = ((const float4*)x)[idx * 2 + 1];
    ((uint4*)g_xh)[idx] = pack8(a, b);
}

// =====================================================================
// Prep 2: W fp32 [k][n] -> k-pair-packed half2 g_wp[z][k2][n].
// =====================================================================
__global__ __launch_bounds__(256) void pack_w_kernel(
    const float* __restrict__ Wq, const float* __restrict__ Wk,
    const float* __restrict__ Wv, const float* __restrict__ Wo)
{
    const int z = blockIdx.z;
    const float* __restrict__ W = (z == 0) ? Wq : (z == 1) ? Wk : (z == 2) ? Wv : Wo;
    int idx = blockIdx.x * 256 + threadIdx.x;
    int k2 = idx >> 8;
    int n4 = (idx & 255) * 4;
    float4 r0 = *(const float4*)(W + (size_t)(2 * k2) * NC + n4);
    float4 r1 = *(const float4*)(W + (size_t)(2 * k2 + 1) * NC + n4);
    uint4 o;
    o.x = h2(r0.x, r1.x); o.y = h2(r0.y, r1.y);
    o.z = h2(r0.z, r1.z); o.w = h2(r0.w, r1.w);
    ((uint4*)(g_wp + (size_t)z * 524288))[idx] = o;
}

// =====================================================================
// Kernel 1: fused QKV projection (fp16 m16n8k16), double-buffered,
// A-fragments via ldmatrix.x4, B-fragments scalar.  (unchanged)
// =====================================================================
__global__ __launch_bounds__(256) void qkv_kernel(
    const float* __restrict__ bq, const float* __restrict__ bk,
    const float* __restrict__ bv)
{
    __shared__ unsigned As[2][128 * 20];
    __shared__ unsigned Bs[2][16 * 132];

    const int z = blockIdx.z;
    const float* __restrict__ bias = (z == 0) ? bq : (z == 1) ? bk : bv;
    const unsigned* __restrict__ Wp = g_wp + (size_t)z * 524288;

    const int tid  = threadIdx.x;
    const int wid  = tid >> 5, lane = tid & 31;
    const int g    = lane >> 2, tg = lane & 3;
    const int r8   = lane & 7,  qd = lane >> 3;
    const int bm   = blockIdx.y * 128, bn = blockIdx.x * 128;
    const int wm   = wid & 1, wn = wid >> 1;

    const int ar0 = tid >> 2,  ac4 = (tid & 3) * 4;
    const int br0 = tid >> 5,  bc4 = (tid & 31) * 4;

    const unsigned aSb = smaddr(&As[0][(wm * 64 + (qd & 1) * 8 + r8) * 20 + (qd >> 1) * 4]);

    uint4 aR[2], bR[2];
    #pragma unroll
    for (int i = 0; i < 2; i++) {
        aR[i] = *(const uint4*)(g_xh + (size_t)(bm + ar0 + 64 * i) * 512 + ac4);
        bR[i] = *(const uint4*)(Wp + (size_t)(br0 + 8 * i) * 1024 + bn + bc4);
    }
    #pragma unroll
    for (int i = 0; i < 2; i++) {
        *(uint4*)&As[0][(ar0 + 64 * i) * 20 + ac4] = aR[i];
        *(uint4*)&Bs[0][(br0 + 8 * i) * 132 + bc4] = bR[i];
    }
    __syncthreads();

    float acc[4][4][4];
    #pragma unroll
    for (int a = 0; a < 4; a++)
        #pragma unroll
        for (int b = 0; b < 4; b++)
            #pragma unroll
            for (int c = 0; c < 4; c++) acc[a][b][c] = 0.f;

    for (int kt = 0; kt < 32; ++kt) {
        const unsigned* Bc = Bs[kt & 1];
        const unsigned aOff = (kt & 1) * 2560u;

        if (kt < 31) {
            #pragma unroll
            for (int i = 0; i < 2; i++) {
                aR[i] = *(const uint4*)(g_xh + (size_t)(bm + ar0 + 64 * i) * 512
                                        + (kt + 1) * 16 + ac4);
                bR[i] = *(const uint4*)(Wp + (size_t)((kt + 1) * 16 + br0 + 8 * i) * 1024
                                        + bn + bc4);
            }
        }
        #pragma unroll
        for (int ks = 0; ks < 2; ks++) {
            const int ku = ks * 8;
            unsigned af[4][4], bf[4][2];
            #pragma unroll
            for (int mt = 0; mt < 4; mt++)
                ldsm4(af[mt], aSb + (aOff + mt * (16 * 20) + ku) * 4);
            #pragma unroll
            for (int nt = 0; nt < 4; nt++) {
                int c0 = wn * 32 + nt * 8 + g;
                bf[nt][0] = Bc[(ku + tg) * 132 + c0];
                bf[nt][1] = Bc[(ku + tg + 4) * 132 + c0];
            }
            #pragma unroll
            for (int mt = 0; mt < 4; mt++)
                #pragma unroll
                for (int nt = 0; nt < 4; nt++)
                    mma16(acc[mt][nt], af[mt], bf[nt]);
        }
        if (kt < 31) {
            unsigned* An = As[(kt + 1) & 1];
            unsigned* Bn = Bs[(kt + 1) & 1];
            #pragma unroll
            for (int i = 0; i < 2; i++) {
                *(uint4*)&An[(ar0 + 64 * i) * 20 + ac4] = aR[i];
                *(uint4*)&Bn[(br0 + 8 * i) * 132 + bc4] = bR[i];
            }
            __syncthreads();
        }
    }

    __half* vt_h = (__half*)g_vt;
    #pragma unroll
    for (int mt = 0; mt < 4; mt++) {
        #pragma unroll
        for (int nt = 0; nt < 4; nt++) {
            int row = bm + wm * 64 + mt * 16 + g;
            int col = bn + wn * 32 + nt * 8 + tg * 2;
            float b0 = bias[col], b1 = bias[col + 1];
            #pragma unroll
            for (int hf = 0; hf < 2; hf++) {
                int m  = row + hf * 8;
                int bb = m >> 10, t = m & 1023;
                int h  = col >> 6, d = col & 63;
                int bh = bb * 16 + h;
                float v0 = acc[mt][nt][hf * 2 + 0] + b0;
                float v1 = acc[mt][nt][hf * 2 + 1] + b1;
                if (z == 0) {
                    g_q[((size_t)(bh * 1024 + t)) * 32 + d / 2] = h2(v0 * 0.125f, v1 * 0.125f);
                } else if (z == 1) {
                    g_k[((size_t)(bh * 1024 + t)) * 32 + d / 2] = h2(v0, v1);
                } else {
                    vt_h[((size_t)(bh * 64 + d)) * 1024 + t]     = __float2half(v0);
                    vt_h[((size_t)(bh * 64 + d + 1)) * 1024 + t] = __float2half(v1);
                }
            }
        }
    }
}

// =====================================================================
// Kernel 2: FLASH attention — P kept in REGISTERS (C-frag of QK^T ==
// A-frag of P@V), S chunked in 64-col halves, cp.async K/V double
// buffer, __launch_bounds__(256,2) for 2 CTAs/SM.
// =====================================================================
__global__ __launch_bounds__(256, 2) void flash_kernel(const int* __restrict__ mask)
{
    extern __shared__ unsigned sm[];
    unsigned* Qs = sm;                          // [128][36]
    unsigned* Ks = Qs + 4608;                   // 2 x [128][36]
    unsigned* Vs = Ks + 2 * 4608;               // 2 x [64][68]
    int*      Ms = (int*)(Vs + 2 * 4352);       // 2 x [128]

    const int bh  = blockIdx.y;
    const int bq  = blockIdx.x * 128;
    const int tid = threadIdx.x;
    const int w   = tid >> 5, lane = tid & 31;
    const int g   = lane >> 2, tg = lane & 3;
    const int r8  = lane & 7,  qd = lane >> 3;

    const unsigned* qptr  = g_q + ((size_t)bh * NT + bq) * 32;
    const unsigned* kbase = g_k + (size_t)bh * NT * 32;
    const unsigned* vbase = g_vt + (size_t)bh * 64 * 512;
    const int*      mrow  = mask + (bh >> 4) * NT;

    const unsigned aQb = smaddr(&Qs[(w * 16 + (qd & 1) * 8 + r8) * 36 + (qd >> 1) * 4]);
    const unsigned bKb = smaddr(&Ks[((qd >> 1) * 8 + r8) * 36 + (qd & 1) * 4]);
    const unsigned bVb = smaddr(&Vs[((qd >> 1) * 8 + r8) * 68 + (qd & 1) * 4]);

    // ---- prologue: Q + tile 0 (synchronous) ----
    #pragma unroll
    for (int i = 0; i < 4; i++) {
        int idx = tid + 256 * i;
        int r = idx >> 3, c4 = (idx & 7) * 4;
        *(uint4*)&Qs[r * 36 + c4] = *(const uint4*)(qptr + (size_t)r * 32 + c4);
        *(uint4*)&Ks[r * 36 + c4] = *(const uint4*)(kbase + (size_t)r * 32 + c4);
    }
    #pragma unroll
    for (int i = 0; i < 4; i++) {
        int idx = tid + 256 * i;
        int r = idx >> 4, c4 = (idx & 15) * 4;
        *(uint4*)&Vs[r * 68 + c4] = *(const uint4*)(vbase + (size_t)r * 512 + c4);
    }
    if (tid < 128) Ms[tid] = mrow[tid];

    float l0 = 0.f, l1 = 0.f;
    float o[8][4];
    #pragma unroll
    for (int i = 0; i < 8; i++)
        #pragma unroll
        for (int j = 0; j < 4; j++) o[i][j] = 0.f;

    for (int t = 0; t < 8; t++) {
        const int cur = t & 1, alt = cur ^ 1;
        cpasync_wait0();
        __syncthreads();

        // issue cp.async for tile t+1 into alt buffers
        if (t < 7) {
            const int tn = (t + 1) * 128;
            #pragma unroll
            for (int i = 0; i < 4; i++) {
                int idx = tid + 256 * i;
                int r = (idx >> 3), c4 = (idx & 7) * 4;
                cpasync16(smaddr(&Ks[alt * 4608 + r * 36 + c4]),
                          kbase + (size_t)(tn + r) * 32 + c4);
                int r2 = (idx >> 4), c42 = (idx & 15) * 4;
                cpasync16(smaddr(&Vs[alt * 4352 + r2 * 68 + c42]),
                          vbase + (size_t)r2 * 512 + tn / 2 + c42);
            }
            if (tid < 32)
                cpasync16(smaddr(&Ms[alt * 128 + tid * 4]), mrow + tn + tid * 4);
            cpasync_commit();
        }

        const unsigned kOff = cur * 4608u * 4u;   // bytes
        const unsigned vOff = cur * 4352u * 4u;
        const int*     Mc   = Ms + cur * 128;

        // ---- S = Q @ K^T in two 64-col halves; P -> registers ----
        unsigned pf[16][2];
        #pragma unroll
        for (int hB = 0; hB < 2; hB++) {
            float s[8][4];
            #pragma unroll
            for (int nt = 0; nt < 8; nt++)
                #pragma unroll
                for (int c = 0; c < 4; c++) s[nt][c] = 0.f;

            #pragma unroll
            for (int ks = 0; ks < 4; ks++) {
                const int ku = ks * 8;
                unsigned af[4];
                ldsm4(af, aQb + ku * 4);
                #pragma unroll
                for (int n2 = 0; n2 < 4; n2++) {
                    unsigned bf[4];
                    ldsm4(bf, bKb + kOff + ((hB * 4 + n2) * (16 * 36) + ku) * 4);
                    mma16(s[2 * n2],     af, bf);
                    mma16(s[2 * n2 + 1], af, bf + 2);
                }
            }
            #pragma unroll
            for (int n2 = 0; n2 < 8; n2++) {
                const int nt = hB * 8 + n2;
                int c0 = nt * 8 + tg * 2;
                float fm0 = (Mc[c0]     != 0) ? 1.f : 0.f;
                float fm1 = (Mc[c0 + 1] != 0) ? 1.f : 0.f;
                float p0 = __expf(s[n2][0]) * fm0;
                float p1 = __expf(s[n2][1]) * fm1;
                float p2 = __expf(s[n2][2]) * fm0;
                float p3 = __expf(s[n2][3]) * fm1;
                l0 += p0 + p1;
                l1 += p2 + p3;
                pf[nt][0] = h2(p0, p1);
                pf[nt][1] = h2(p2, p3);
            }
        }

        // ---- O += P @ V  (A-fragments straight from pf registers) ----
        #pragma unroll
        for (int ks = 0; ks < 8; ks++) {
            unsigned af[4];
            af[0] = pf[2 * ks][0];
            af[1] = pf[2 * ks][1];
            af[2] = pf[2 * ks + 1][0];
            af[3] = pf[2 * ks + 1][1];
            #pragma unroll
            for (int ntp = 0; ntp < 4; ntp++) {
                unsigned bf[4];
                ldsm4(bf, bVb + vOff + (ntp * (16 * 68) + ks * 8) * 4);
                mma16(o[2 * ntp],     af, bf);
                mma16(o[2 * ntp + 1], af, bf + 2);
            }
        }
    }

    // ---- epilogue ----
    #pragma unroll
    for (int off = 1; off <= 2; off <<= 1) {
        l0 += __shfl_xor_sync(0xffffffffu, l0, off);
        l1 += __shfl_xor_sync(0xffffffffu, l1, off);
    }
    const int b_ = bh >> 4, h = bh & 15;
    float inv0 = 1.0f / l0, inv1 = 1.0f / l1;
    #pragma unroll
    for (int nt = 0; nt < 8; nt++) {
        int d = nt * 8 + tg * 2;
        int q0 = bq + w * 16 + g;
        g_attn[((size_t)(b_ * 1024 + q0)) * 512 + (h * 64 + d) / 2]
            = h2(o[nt][0] * inv0, o[nt][1] * inv0);
        g_attn[((size_t)(b_ * 1024 + q0 + 8)) * 512 + (h * 64 + d) / 2]
            = h2(o[nt][2] * inv1, o[nt][3] * inv1);
    }
}

// =====================================================================
// Kernel 3: output projection — A via ldmatrix, B scalar. (unchanged)
// =====================================================================
__global__ __launch_bounds__(256) void proj_kernel(const float* __restrict__ bo)
{
    __shared__ unsigned As[2][128 * 20];
    __shared__ unsigned Bs[2][16 * 132];

    const unsigned* __restrict__ Wp = g_wp + (size_t)3 * 524288;

    const int tid  = threadIdx.x;
    const int wid  = tid >> 5, lane = tid & 31;
    const int g    = lane >> 2, tg = lane & 3;
    const int r8   = lane & 7,  qd = lane >> 3;
    const int bm   = blockIdx.y * 128, bn = blockIdx.x * 128;
    const int wm   = wid & 1, wn = wid >> 1;

    const int ar0 = tid >> 2,  ac4 = (tid & 3) * 4;
    const int br0 = tid >> 5,  bc4 = (tid & 31) * 4;

    const unsigned aSb = smaddr(&As[0][(wm * 64 + (qd & 1) * 8 + r8) * 20 + (qd >> 1) * 4]);

    uint4 aR[2], bR[2];
    #pragma unroll
    for (int i = 0; i < 2; i++) {
        aR[i] = *(const uint4*)(g_attn + (size_t)(bm + ar0 + 64 * i) * 512 + ac4);
        bR[i] = *(const uint4*)(Wp + (size_t)(br0 + 8 * i) * 1024 + bn + bc4);
    }
    #pragma unroll
    for (int i = 0; i < 2; i++) {
        *(uint4*)&As[0][(ar0 + 64 * i) * 20 + ac4] = aR[i];
        *(uint4*)&Bs[0][(br0 + 8 * i) * 132 + bc4] = bR[i];
    }
    __syncthreads();

    float acc[4][4][4];
    #pragma unroll
    for (int a = 0; a < 4; a++)
        #pragma unroll
        for (int b = 0; b < 4; b++)
            #pragma unroll
            for (int c = 0; c < 4; c++) acc[a][b][c] = 0.f;

    for (int kt = 0; kt < 32; ++kt) {
        const unsigned* Bc = Bs[kt & 1];
        const unsigned aOff = (kt & 1) * 2560u;

        if (kt < 31) {
            #pragma unroll
            for (int i = 0; i < 2; i++) {
                aR[i] = *(const uint4*)(g_attn + (size_t)(bm + ar0 + 64 * i) * 512
                                        + (kt + 1) * 16 + ac4);
                bR[i] = *(const uint4*)(Wp + (size_t)((kt + 1) * 16 + br0 + 8 * i) * 1024
                                        + bn + bc4);
            }
        }
        #pragma unroll
        for (int ks = 0; ks < 2; ks++) {
            const int ku = ks * 8;
            unsigned af[4][4], bf[4][2];
            #pragma unroll
            for (int mt = 0; mt < 4; mt++)
                ldsm4(af[mt], aSb + (aOff + mt * (16 * 20) + ku) * 4);
            #pragma unroll
            for (int nt = 0; nt < 4; nt++) {
                int c0 = wn * 32 + nt * 8 + g;
                bf[nt][0] = Bc[(ku + tg) * 132 + c0];
                bf[nt][1] = Bc[(ku + tg + 4) * 132 + c0];
            }
            #pragma unroll
            for (int mt = 0; mt < 4; mt++)
                #pragma unroll
                for (int nt = 0; nt < 4; nt++)
                    mma16(acc[mt][nt], af[mt], bf[nt]);
        }
        if (kt < 31) {
            unsigned* An = As[(kt + 1) & 1];
            unsigned* Bn = Bs[(kt + 1) & 1];
            #pragma unroll
            for (int i = 0; i < 2; i++) {
                *(uint4*)&An[(ar0 + 64 * i) * 20 + ac4] = aR[i];
                *(uint4*)&Bn[(br0 + 8 * i) * 132 + bc4] = bR[i];
            }
            __syncthreads();
        }
    }

    #pragma unroll
    for (int mt = 0; mt < 4; mt++) {
        #pragma unroll
        for (int nt = 0; nt < 4; nt++) {
            int row = bm + wm * 64 + mt * 16 + g;
            int col = bn + wn * 32 + nt * 8 + tg * 2;
            float b0 = bo[col], b1 = bo[col + 1];
            #pragma unroll
            for (int hf = 0; hf < 2; hf++) {
                int m = row + hf * 8;
                float2 val = make_float2(acc[mt][nt][hf * 2 + 0] + b0,
                                         acc[mt][nt][hf * 2 + 1] + b1);
                *(float2*)&g_proj[(size_t)m * NC + col] = val;
            }
        }
    }
}

// =====================================================================
// Kernel 4: LayerNorm.
// =====================================================================
__global__ __launch_bounds__(256) void ln_kernel(
    const float* __restrict__ gamma, const float* __restrict__ beta,
    float* __restrict__ out)
{
    __shared__ float redS[8];
    __shared__ float redQ[8];
    const int tid = threadIdx.x;
    const float* p = g_proj + (size_t)blockIdx.x * NC;

    float4 v = ((const float4*)p)[tid];
    float s  = v.x + v.y + v.z + v.w;
    float ss = v.x * v.x + v.y * v.y + v.z * v.z + v.w * v.w;
    #pragma unroll
    for (int o = 16; o > 0; o >>= 1) {
        s  += __shfl_xor_sync(0xffffffffu, s,  o);
        ss += __shfl_xor_sync(0xffffffffu, ss, o);
    }
    if ((tid & 31) == 0) { redS[tid >> 5] = s; redQ[tid >> 5] = ss; }
    __syncthreads();
    float S = 0.f, Q = 0.f;
    #pragma unroll
    for (int w = 0; w < 8; w++) { S += redS[w]; Q += redQ[w]; }

    float mu  = S * (1.0f / 1024.0f);
    float var = Q * (1.0f / 1024.0f) - mu * mu;
    var = fmaxf(var, 0.0f);
    float rstd = rsqrtf(var + 1e-5f);

    float4 gv = ((const float4*)gamma)[tid];
    float4 bv = ((const float4*)beta)[tid];
    float4 o;
    o.x = (v.x - mu) * rstd * gv.x + bv.x;
    o.y = (v.y - mu) * rstd * gv.y + bv.y;
    o.z = (v.z - mu) * rstd * gv.z + bv.z;
    o.w = (v.w - mu) * rstd * gv.w + bv.w;
    ((float4*)(out + (size_t)blockIdx.x * NC))[tid] = o;
}

// =====================================================================
extern "C" void kernel_launch(void* const* d_in, const int* in_sizes, int n_in,
                              void* d_out, int out_size)
{
    const float* x    = (const float*)d_in[0];
    const int*   mask = (const int*)  d_in[1];
    const float* Wq   = (const float*)d_in[2];
    const float* bq   = (const float*)d_in[3];
    const float* Wk   = (const float*)d_in[4];
    const float* bk   = (const float*)d_in[5];
    const float* Wv   = (const float*)d_in[6];
    const float* bv   = (const float*)d_in[7];
    const float* Wo   = (const float*)d_in[8];
    const float* bo   = (const float*)d_in[9];
    const float* lg   = (const float*)d_in[10];
    const float* lb   = (const float*)d_in[11];
    float* out = (float*)d_out;

    // Qs + 2*Ks + 2*Vs (uints) + 2*Ms (ints) = 91,136 B -> 2 CTAs/SM fit
    const int FLASH_SMEM = (4608 + 2 * 4608 + 2 * 4352) * 4 + 2 * 128 * 4;
    cudaFuncSetAttribute(flash_kernel,
                         cudaFuncAttributeMaxDynamicSharedMemorySize, FLASH_SMEM);

    cvt_x_kernel <<<2048, 256>>>(x);
    pack_w_kernel<<<dim3(512, 1, 4), 256>>>(Wq, Wk, Wv, Wo);
    qkv_kernel   <<<dim3(8, 32, 3), 256>>>(bq, bk, bv);
    flash_kernel <<<dim3(8, 64), 256, FLASH_SMEM>>>(mask);
    proj_kernel  <<<dim3(8, 32), 256>>>(bo);
    ln_kernel    <<<4096, 256>>>(lg, lb, out);
}